// round 3
// baseline (speedup 1.0000x reference)
#include <cuda_runtime.h>

// Problem constants (B=8192, T=2048, H=51)
#define B_   8192
#define T_   2048
#define H_   51
#define G4   204    // 4*H
#define JP   208    // padded gate-column count (multiple of 16)
#define GP   210    // gates smem pitch (even, 8B-alignable, low-conflict)
#define M_   64     // batch rows per CTA
#define NTH  256

typedef unsigned long long u64;

// ---------- packed fp32x2 helpers (Blackwell dual-rate fp32 path) ----------
__device__ __forceinline__ u64 pack2(float lo, float hi) {
    u64 d; asm("mov.b64 %0, {%1, %2};" : "=l"(d) : "f"(lo), "f"(hi)); return d;
}
__device__ __forceinline__ u64 fma2(u64 a, u64 b, u64 c) {
    u64 d; asm("fma.rn.f32x2 %0, %1, %2, %3;" : "=l"(d) : "l"(a), "l"(b), "l"(c)); return d;
}
// ---------- accurate fast activations (MUFU ex2 + rcp, ~fp32 accuracy) ----------
__device__ __forceinline__ float ex2f(float x) { float r; asm("ex2.approx.f32 %0, %1;" : "=f"(r) : "f"(x)); return r; }
__device__ __forceinline__ float rcpf(float x) { float r; asm("rcp.approx.f32 %0, %1;" : "=f"(r) : "f"(x)); return r; }
__device__ __forceinline__ float sigm(float x) {
    return rcpf(1.0f + ex2f(-1.4426950408889634f * x));
}
__device__ __forceinline__ float tanh_(float x) {
    // tanh(x) = 1 - 2/(exp(2x)+1); exact saturation at both ends, no NaNs
    float e = ex2f(2.8853900817779268f * x);
    return 1.0f - 2.0f * rcpf(e + 1.0f);
}

// Smem layout (float offsets)
#define OFF_W1    0
#define OFF_W2A   10608          // 51*208
#define OFF_W2B   21216
#define OFF_GT    31824          // 64*210 = 13440
#define OFF_H1T   45264          // 51*64 = 3264
#define OFF_H2T   48528
#define OFF_B1    51792          // 208
#define OFF_B2    52000
#define OFF_WI1   52208
#define OFF_WL    52416          // 51 + b_lin at [51]
#define SMEM_FLOATS 52468

__global__ __launch_bounds__(NTH, 1)
void lstm_rnn_kernel(const float* __restrict__ x,
                     const float* __restrict__ Wih1, const float* __restrict__ Whh1,
                     const float* __restrict__ bih1, const float* __restrict__ bhh1,
                     const float* __restrict__ Wih2, const float* __restrict__ Whh2,
                     const float* __restrict__ bih2, const float* __restrict__ bhh2,
                     const float* __restrict__ Wlin, const float* __restrict__ blin,
                     float* __restrict__ out)
{
    extern __shared__ float sm[];
    float* W1s  = sm + OFF_W1;   // [51][208] k-major
    float* W2as = sm + OFF_W2A;  // W_ih2 transposed
    float* W2bs = sm + OFF_W2B;  // W_hh2 transposed
    float* GT   = sm + OFF_GT;   // gates [64][210]
    float* H1T  = sm + OFF_H1T;  // h1 transposed [51][64]
    float* H2T  = sm + OFF_H2T;  // h2 transposed [51][64]
    float* B1s  = sm + OFF_B1;
    float* B2s  = sm + OFF_B2;
    float* WI1s = sm + OFF_WI1;
    float* WLs  = sm + OFF_WL;

    const int tid = threadIdx.x;

    // ---------------- stage weights (transpose to k-major) ----------------
    for (int idx = tid; idx < G4 * H_; idx += NTH) {
        int j = idx / H_, k = idx - j * H_;
        W1s [k * JP + j] = Whh1[idx];
        W2as[k * JP + j] = Wih2[idx];
        W2bs[k * JP + j] = Whh2[idx];
    }
    for (int idx = tid; idx < H_ * 4; idx += NTH) {       // zero pad cols 204..207
        int k = idx >> 2, j = G4 + (idx & 3);
        W1s[k * JP + j] = 0.f; W2as[k * JP + j] = 0.f; W2bs[k * JP + j] = 0.f;
    }
    for (int j = tid; j < JP; j += NTH) {
        bool v = (j < G4);
        B1s[j]  = v ? (bih1[j] + bhh1[j]) : 0.f;
        B2s[j]  = v ? (bih2[j] + bhh2[j]) : 0.f;
        WI1s[j] = v ? Wih1[j] : 0.f;
    }
    if (tid < 52) WLs[tid] = (tid < H_) ? Wlin[tid] : blin[0];
    for (int idx = tid; idx < H_ * M_; idx += NTH) { H1T[idx] = 0.f; H2T[idx] = 0.f; }
    __syncthreads();

    // GEMM tiling: 8 j-groups x 32 m-groups; each thread: 2 m rows x 26 j cols (13 f32x2 pairs)
    const int jg    = tid & 7;
    const int mg    = tid >> 3;
    const int jbase = jg * 26;
    const int mbase = mg * 2;
    const int m0    = blockIdx.x * M_;

    float c1r[13], c2r[13];
#pragma unroll
    for (int i = 0; i < 13; i++) { c1r[i] = 0.f; c2r[i] = 0.f; }

    float xv0 = x[(size_t)(m0 + mbase + 0) * T_];
    float xv1 = x[(size_t)(m0 + mbase + 1) * T_];

    for (int t = 0; t < T_; ++t) {
        // ============ Phase G1: gates1 = h1 @ Whh1^T + x*Wih1 + b1 ============
        int tn = (t + 1 < T_) ? (t + 1) : (T_ - 1);
        float xn0 = x[(size_t)(m0 + mbase + 0) * T_ + tn];   // prefetch next x
        float xn1 = x[(size_t)(m0 + mbase + 1) * T_ + tn];

        u64 acc0[13], acc1[13];
        {
            u64 xd0 = pack2(xv0, xv0), xd1 = pack2(xv1, xv1);
#pragma unroll
            for (int jj = 0; jj < 13; ++jj) {
                int j  = jbase + 2 * jj;
                u64 b2 = *(const u64*)(B1s + j);
                u64 w2 = *(const u64*)(WI1s + j);
                acc0[jj] = fma2(xd0, w2, b2);
                acc1[jj] = fma2(xd1, w2, b2);
            }
        }
#pragma unroll 3
        for (int k = 0; k < H_; ++k) {
            float2 h = *(const float2*)(H1T + k * M_ + mbase);
            u64 h0 = pack2(h.x, h.x), h1 = pack2(h.y, h.y);
            const u64* wr = (const u64*)(W1s + k * JP + jbase);
#pragma unroll
            for (int jj = 0; jj < 13; ++jj) {
                u64 w2 = wr[jj];
                acc0[jj] = fma2(h0, w2, acc0[jj]);
                acc1[jj] = fma2(h1, w2, acc1[jj]);
            }
        }
#pragma unroll
        for (int jj = 0; jj < 13; ++jj) {
            *(u64*)(GT + (mbase + 0) * GP + jbase + 2 * jj) = acc0[jj];
            *(u64*)(GT + (mbase + 1) * GP + jbase + 2 * jj) = acc1[jj];
        }
        __syncthreads();

        // ============ Phase A1: layer-1 cell update (+ y of step t-1) ============
        if (tid < M_ && t > 0) {
            float y = WLs[H_];
#pragma unroll
            for (int u = 0; u < H_; ++u) y = fmaf(WLs[u], H2T[u * M_ + tid], y);
            out[(size_t)(m0 + tid) * T_ + (t - 1)] = y;
        }
#pragma unroll
        for (int it = 0; it < 13; ++it) {
            int p = tid + it * NTH;
            if (p < H_ * M_) {
                int u = p >> 6, m = p & (M_ - 1);
                const float* g = GT + m * GP;
                float ig = g[u], fg = g[H_ + u], gg = g[2 * H_ + u], og = g[3 * H_ + u];
                float c = sigm(fg) * c1r[it] + sigm(ig) * tanh_(gg);
                c1r[it] = c;
                H1T[u * M_ + m] = sigm(og) * tanh_(c);
            }
        }
        xv0 = xn0; xv1 = xn1;
        __syncthreads();

        // ============ Phase G2: gates2 = h1_new @ Wih2^T + h2 @ Whh2^T + b2 ============
#pragma unroll
        for (int jj = 0; jj < 13; ++jj) {
            u64 b2 = *(const u64*)(B2s + jbase + 2 * jj);
            acc0[jj] = b2; acc1[jj] = b2;
        }
#pragma unroll 3
        for (int k = 0; k < H_; ++k) {
            float2 h = *(const float2*)(H1T + k * M_ + mbase);
            u64 h0 = pack2(h.x, h.x), h1 = pack2(h.y, h.y);
            const u64* wr = (const u64*)(W2as + k * JP + jbase);
#pragma unroll
            for (int jj = 0; jj < 13; ++jj) {
                u64 w2 = wr[jj];
                acc0[jj] = fma2(h0, w2, acc0[jj]);
                acc1[jj] = fma2(h1, w2, acc1[jj]);
            }
        }
#pragma unroll 3
        for (int k = 0; k < H_; ++k) {
            float2 h = *(const float2*)(H2T + k * M_ + mbase);
            u64 h0 = pack2(h.x, h.x), h1 = pack2(h.y, h.y);
            const u64* wr = (const u64*)(W2bs + k * JP + jbase);
#pragma unroll
            for (int jj = 0; jj < 13; ++jj) {
                u64 w2 = wr[jj];
                acc0[jj] = fma2(h0, w2, acc0[jj]);
                acc1[jj] = fma2(h1, w2, acc1[jj]);
            }
        }
#pragma unroll
        for (int jj = 0; jj < 13; ++jj) {
            *(u64*)(GT + (mbase + 0) * GP + jbase + 2 * jj) = acc0[jj];
            *(u64*)(GT + (mbase + 1) * GP + jbase + 2 * jj) = acc1[jj];
        }
        __syncthreads();

        // ============ Phase A2: layer-2 cell update ============
#pragma unroll
        for (int it = 0; it < 13; ++it) {
            int p = tid + it * NTH;
            if (p < H_ * M_) {
                int u = p >> 6, m = p & (M_ - 1);
                const float* g = GT + m * GP;
                float ig = g[u], fg = g[H_ + u], gg = g[2 * H_ + u], og = g[3 * H_ + u];
                float c = sigm(fg) * c2r[it] + sigm(ig) * tanh_(gg);
                c2r[it] = c;
                H2T[u * M_ + m] = sigm(og) * tanh_(c);
            }
        }
        __syncthreads();
    }

    // final output for t = T-1
    if (tid < M_) {
        float y = WLs[H_];
#pragma unroll
        for (int u = 0; u < H_; ++u) y = fmaf(WLs[u], H2T[u * M_ + tid], y);
        out[(size_t)(m0 + tid) * T_ + (T_ - 1)] = y;
    }
}

extern "C" void kernel_launch(void* const* d_in, const int* in_sizes, int n_in,
                              void* d_out, int out_size) {
    const float* x    = (const float*)d_in[0];
    const float* Wih1 = (const float*)d_in[1];
    const float* Whh1 = (const float*)d_in[2];
    const float* bih1 = (const float*)d_in[3];
    const float* bhh1 = (const float*)d_in[4];
    const float* Wih2 = (const float*)d_in[5];
    const float* Whh2 = (const float*)d_in[6];
    const float* bih2 = (const float*)d_in[7];
    const float* bhh2 = (const float*)d_in[8];
    const float* Wlin = (const float*)d_in[9];
    const float* blin = (const float*)d_in[10];
    float* out = (float*)d_out;

    size_t smem = SMEM_FLOATS * sizeof(float);   // ~205 KB
    cudaFuncSetAttribute(lstm_rnn_kernel,
                         cudaFuncAttributeMaxDynamicSharedMemorySize, (int)smem);
    lstm_rnn_kernel<<<B_ / M_, NTH, smem>>>(x, Wih1, Whh1, bih1, bhh1,
                                            Wih2, Whh2, bih2, bhh2,
                                            Wlin, blin, out);
}

// round 4
// speedup vs baseline: 1.4274x; 1.4274x over previous
#include <cuda_runtime.h>

// B=8192, T=2048, H=51
#define B_   8192
#define T_   2048
#define H_   51
#define UPAD 52            // padded hidden (u) count
#define CPAD 208           // UPAD*4 interleaved gate columns per layer
#define M_   64            // batch rows per CTA
#define NTH  256

typedef unsigned long long u64;

// ---------- packed fp32x2 (Blackwell dual-rate fp32) ----------
__device__ __forceinline__ u64 pack2(float lo, float hi) {
    u64 d; asm("mov.b64 %0, {%1, %2};" : "=l"(d) : "f"(lo), "f"(hi)); return d;
}
__device__ __forceinline__ void unpack2(u64 v, float& lo, float& hi) {
    asm("mov.b64 {%0, %1}, %2;" : "=f"(lo), "=f"(hi) : "l"(v));
}
__device__ __forceinline__ u64 fma2(u64 a, u64 b, u64 c) {
    u64 d; asm("fma.rn.f32x2 %0, %1, %2, %3;" : "=l"(d) : "l"(a), "l"(b), "l"(c)); return d;
}
// ---------- accurate fast activations ----------
__device__ __forceinline__ float ex2f(float x) { float r; asm("ex2.approx.f32 %0, %1;" : "=f"(r) : "f"(x)); return r; }
__device__ __forceinline__ float rcpf(float x) { float r; asm("rcp.approx.f32 %0, %1;" : "=f"(r) : "f"(x)); return r; }
__device__ __forceinline__ float sigm(float x) {
    return rcpf(1.0f + ex2f(-1.4426950408889634f * x));
}
__device__ __forceinline__ float tanh_(float x) {
    float e = ex2f(2.8853900817779268f * x);
    return 1.0f - 2.0f * rcpf(e + 1.0f);
}

// Smem layout (float offsets)
#define OFF_W1   0                        // [51][208] gate-interleaved
#define OFF_W2A  10608
#define OFF_W2B  21216
#define OFF_H1   31824                    // double buffer [2][52*64]
#define OFF_H2   38480                    // double buffer [2][52*64]
#define OFF_B1   45136                    // 208
#define OFF_WI1  45344                    // 208
#define OFF_B2   45552                    // 208
#define OFF_WL   45760                    // 53 (pad to 56)
#define OFF_YP   45816                    // [2][4*64]
#define SMEM_FLOATS 46328                 // ~185 KB

#define HBUF 3328                         // 52*64

__global__ __launch_bounds__(NTH, 1)
void lstm_rnn_kernel(const float* __restrict__ x,
                     const float* __restrict__ Wih1, const float* __restrict__ Whh1,
                     const float* __restrict__ bih1, const float* __restrict__ bhh1,
                     const float* __restrict__ Wih2, const float* __restrict__ Whh2,
                     const float* __restrict__ bih2, const float* __restrict__ bhh2,
                     const float* __restrict__ Wlin, const float* __restrict__ blin,
                     float* __restrict__ out)
{
    extern __shared__ float sm[];
    float* W1s  = sm + OFF_W1;
    float* W2as = sm + OFF_W2A;
    float* W2bs = sm + OFF_W2B;
    float* H1   = sm + OFF_H1;
    float* H2   = sm + OFF_H2;
    float* B1s  = sm + OFF_B1;
    float* WI1s = sm + OFF_WI1;
    float* B2s  = sm + OFF_B2;
    float* WLs  = sm + OFF_WL;
    float* YP   = sm + OFF_YP;

    const int tid = threadIdx.x;

    // ---- stage weights: gate-interleaved, k-major: W[k][u*4+g] = Wxx[g*51+u][k]
    for (int idx = tid; idx < H_ * CPAD; idx += NTH) {
        int kk = idx / CPAD, c = idx - kk * CPAD;
        int u = c >> 2, g = c & 3;
        float w1 = 0.f, wa = 0.f, wb = 0.f;
        if (u < H_) {
            int j = g * H_ + u;
            w1 = Whh1[j * H_ + kk];
            wa = Wih2[j * H_ + kk];
            wb = Whh2[j * H_ + kk];
        }
        W1s[idx] = w1; W2as[idx] = wa; W2bs[idx] = wb;
    }
    for (int c = tid; c < CPAD; c += NTH) {
        int u = c >> 2, g = c & 3;
        bool v = (u < H_);
        int j = g * H_ + u;
        B1s[c]  = v ? (bih1[j] + bhh1[j]) : 0.f;
        WI1s[c] = v ? Wih1[j] : 0.f;
        B2s[c]  = v ? (bih2[j] + bhh2[j]) : 0.f;
    }
    if (tid < 53) WLs[tid] = (tid < H_) ? Wlin[tid] : ((tid == 52) ? blin[0] : 0.f);
    for (int idx = tid; idx < 2 * HBUF; idx += NTH) { H1[idx] = 0.f; H2[idx] = 0.f; }
    for (int idx = tid; idx < 512; idx += NTH) YP[idx] = 0.f;
    __syncthreads();

    // roles: warps 0-3 (grp 0) = layer 1 + y writer; warps 4-7 (grp 1) = layer 2
    const int grp  = tid >> 7;
    const int lt   = tid & 127;
    const int ug   = lt >> 5;        // 0..3 (warp-uniform): u range [ug*13, ug*13+13)
    const int mg   = lt & 31;        // 0..31
    const int cb   = ug * 52;        // interleaved col base
    const int mloc = mg * 2;         // 2 m-rows per thread
    const int m0   = blockIdx.x * M_;

    float c1r[26], c2r[26];
#pragma unroll
    for (int q = 0; q < 26; ++q) { c1r[q] = 0.f; c2r[q] = 0.f; }

    float xv0 = 0.f, xv1 = 0.f;
    if (grp == 0) {
        xv0 = x[(size_t)(m0 + mloc + 0) * T_];
        xv1 = x[(size_t)(m0 + mloc + 1) * T_];
    }

    for (int i = 0; i <= T_ + 1; ++i) {
        if (grp == 0) {
            // ---- y writer: reduce partials of step i-2 ----
            if (lt < 64 && i >= 2) {
                const float* yp = YP + ((i - 1) & 1) * 256;
                float y = WLs[52] + yp[lt] + yp[64 + lt] + yp[128 + lt] + yp[192 + lt];
                out[(size_t)(m0 + lt) * T_ + (i - 2)] = y;
            }
            // ---- layer 1, step t = i ----
            if (i < T_) {
                int tn = (i + 1 < T_) ? (i + 1) : (T_ - 1);
                float xn0 = x[(size_t)(m0 + mloc + 0) * T_ + tn];
                float xn1 = x[(size_t)(m0 + mloc + 1) * T_ + tn];

                u64 acc[52];
                {
                    u64 x0 = pack2(xv0, xv0), x1 = pack2(xv1, xv1);
                    const ulonglong2* Bp = (const ulonglong2*)(B1s + cb);
                    const ulonglong2* Wp = (const ulonglong2*)(WI1s + cb);
#pragma unroll
                    for (int q = 0; q < 13; ++q) {
                        ulonglong2 b2 = Bp[q], w2 = Wp[q];
                        acc[4*q+0] = fma2(x0, w2.x, b2.x);
                        acc[4*q+1] = fma2(x1, w2.x, b2.x);
                        acc[4*q+2] = fma2(x0, w2.y, b2.y);
                        acc[4*q+3] = fma2(x1, w2.y, b2.y);
                    }
                }
                const float* Hr = H1 + ((i + 1) & 1) * HBUF;   // h1(i-1)
                const float* wb0 = W1s + cb;
#pragma unroll 3
                for (int kk = 0; kk < H_; ++kk) {
                    float2 h = *(const float2*)(Hr + kk * 64 + mloc);
                    u64 h0 = pack2(h.x, h.x), h1 = pack2(h.y, h.y);
                    const ulonglong2* wr = (const ulonglong2*)(wb0 + kk * CPAD);
#pragma unroll
                    for (int q = 0; q < 13; ++q) {
                        ulonglong2 w2 = wr[q];
                        acc[4*q+0] = fma2(h0, w2.x, acc[4*q+0]);
                        acc[4*q+1] = fma2(h1, w2.x, acc[4*q+1]);
                        acc[4*q+2] = fma2(h0, w2.y, acc[4*q+2]);
                        acc[4*q+3] = fma2(h1, w2.y, acc[4*q+3]);
                    }
                }
                // in-register activation -> h1(i)
                float* Hw = H1 + (i & 1) * HBUF;
#pragma unroll
                for (int q = 0; q < 13; ++q) {
                    float hh0, hh1;
                    {
                        float iv, fv, gv, ov;
                        unpack2(acc[4*q+0], iv, fv);
                        unpack2(acc[4*q+2], gv, ov);
                        float c = sigm(fv) * c1r[2*q+0] + sigm(iv) * tanh_(gv);
                        c1r[2*q+0] = c;
                        hh0 = sigm(ov) * tanh_(c);
                    }
                    {
                        float iv, fv, gv, ov;
                        unpack2(acc[4*q+1], iv, fv);
                        unpack2(acc[4*q+3], gv, ov);
                        float c = sigm(fv) * c1r[2*q+1] + sigm(iv) * tanh_(gv);
                        c1r[2*q+1] = c;
                        hh1 = sigm(ov) * tanh_(c);
                    }
                    *(float2*)(Hw + (ug * 13 + q) * 64 + mloc) = make_float2(hh0, hh1);
                }
                xv0 = xn0; xv1 = xn1;
            }
        } else {
            // ---- layer 2, step t = i-1 ----
            if (i >= 1 && i <= T_) {
                u64 acc[52];
                {
                    const ulonglong2* Bp = (const ulonglong2*)(B2s + cb);
#pragma unroll
                    for (int q = 0; q < 13; ++q) {
                        ulonglong2 b2 = Bp[q];
                        acc[4*q+0] = b2.x; acc[4*q+1] = b2.x;
                        acc[4*q+2] = b2.y; acc[4*q+3] = b2.y;
                    }
                }
                const float* H1r = H1 + ((i - 1) & 1) * HBUF;  // h1(i-1)
                const float* H2r = H2 + ((i - 1) & 1) * HBUF;  // h2(i-2)
                const float* wa0 = W2as + cb;
                const float* wb0 = W2bs + cb;
#pragma unroll 2
                for (int kk = 0; kk < H_; ++kk) {
                    float2 ha = *(const float2*)(H1r + kk * 64 + mloc);
                    float2 hb = *(const float2*)(H2r + kk * 64 + mloc);
                    u64 a0 = pack2(ha.x, ha.x), a1 = pack2(ha.y, ha.y);
                    u64 b0 = pack2(hb.x, hb.x), b1 = pack2(hb.y, hb.y);
                    const ulonglong2* wra = (const ulonglong2*)(wa0 + kk * CPAD);
                    const ulonglong2* wrb = (const ulonglong2*)(wb0 + kk * CPAD);
#pragma unroll
                    for (int q = 0; q < 13; ++q) {
                        ulonglong2 wa = wra[q];
                        acc[4*q+0] = fma2(a0, wa.x, acc[4*q+0]);
                        acc[4*q+1] = fma2(a1, wa.x, acc[4*q+1]);
                        acc[4*q+2] = fma2(a0, wa.y, acc[4*q+2]);
                        acc[4*q+3] = fma2(a1, wa.y, acc[4*q+3]);
                        ulonglong2 wbv = wrb[q];
                        acc[4*q+0] = fma2(b0, wbv.x, acc[4*q+0]);
                        acc[4*q+1] = fma2(b1, wbv.x, acc[4*q+1]);
                        acc[4*q+2] = fma2(b0, wbv.y, acc[4*q+2]);
                        acc[4*q+3] = fma2(b1, wbv.y, acc[4*q+3]);
                    }
                }
                // in-register activation -> h2(i-1), plus y partials
                float* Hw = H2 + (i & 1) * HBUF;
                float py0 = 0.f, py1 = 0.f;
#pragma unroll
                for (int q = 0; q < 13; ++q) {
                    float hh0, hh1;
                    {
                        float iv, fv, gv, ov;
                        unpack2(acc[4*q+0], iv, fv);
                        unpack2(acc[4*q+2], gv, ov);
                        float c = sigm(fv) * c2r[2*q+0] + sigm(iv) * tanh_(gv);
                        c2r[2*q+0] = c;
                        hh0 = sigm(ov) * tanh_(c);
                    }
                    {
                        float iv, fv, gv, ov;
                        unpack2(acc[4*q+1], iv, fv);
                        unpack2(acc[4*q+3], gv, ov);
                        float c = sigm(fv) * c2r[2*q+1] + sigm(iv) * tanh_(gv);
                        c2r[2*q+1] = c;
                        hh1 = sigm(ov) * tanh_(c);
                    }
                    *(float2*)(Hw + (ug * 13 + q) * 64 + mloc) = make_float2(hh0, hh1);
                    float wl = WLs[ug * 13 + q];
                    py0 = fmaf(wl, hh0, py0);
                    py1 = fmaf(wl, hh1, py1);
                }
                *(float2*)(YP + (i & 1) * 256 + ug * 64 + mloc) = make_float2(py0, py1);
            }
        }
        __syncthreads();
    }
}

extern "C" void kernel_launch(void* const* d_in, const int* in_sizes, int n_in,
                              void* d_out, int out_size) {
    const float* x    = (const float*)d_in[0];
    const float* Wih1 = (const float*)d_in[1];
    const float* Whh1 = (const float*)d_in[2];
    const float* bih1 = (const float*)d_in[3];
    const float* bhh1 = (const float*)d_in[4];
    const float* Wih2 = (const float*)d_in[5];
    const float* Whh2 = (const float*)d_in[6];
    const float* bih2 = (const float*)d_in[7];
    const float* bhh2 = (const float*)d_in[8];
    const float* Wlin = (const float*)d_in[9];
    const float* blin = (const float*)d_in[10];
    float* out = (float*)d_out;

    size_t smem = SMEM_FLOATS * sizeof(float);   // ~185 KB
    cudaFuncSetAttribute(lstm_rnn_kernel,
                         cudaFuncAttributeMaxDynamicSharedMemorySize, (int)smem);
    lstm_rnn_kernel<<<B_ / M_, NTH, smem>>>(x, Wih1, Whh1, bih1, bhh1,
                                            Wih2, Whh2, bih2, bhh2,
                                            Wlin, blin, out);
}

// round 5
// speedup vs baseline: 1.4531x; 1.0180x over previous
#include <cuda_runtime.h>

// B=8192, T=2048, H=51
#define B_   8192
#define T_   2048
#define H_   51
#define CP   208           // 52*4 gate-interleaved columns (u=51 is zero pad)
#define M_   64
#define NTH  256

typedef unsigned long long u64;

__device__ __forceinline__ u64 pack2(float lo, float hi) {
    u64 d; asm("mov.b64 %0, {%1, %2};" : "=l"(d) : "f"(lo), "f"(hi)); return d;
}
__device__ __forceinline__ void unpack2(u64 v, float& lo, float& hi) {
    asm("mov.b64 {%0, %1}, %2;" : "=f"(lo), "=f"(hi) : "l"(v));
}
__device__ __forceinline__ u64 fma2(u64 a, u64 b, u64 c) {
    u64 d; asm("fma.rn.f32x2 %0, %1, %2, %3;" : "=l"(d) : "l"(a), "l"(b), "l"(c)); return d;
}
__device__ __forceinline__ float ex2f(float x) { float r; asm("ex2.approx.f32 %0, %1;" : "=f"(r) : "f"(x)); return r; }
__device__ __forceinline__ float rcpf(float x) { float r; asm("rcp.approx.f32 %0, %1;" : "=f"(r) : "f"(x)); return r; }
__device__ __forceinline__ float sigm(float x) {
    return rcpf(1.0f + ex2f(-1.4426950408889634f * x));
}
__device__ __forceinline__ float tanh_(float x) {
    float e = ex2f(2.8853900817779268f * x);
    return 1.0f - 2.0f * rcpf(e + 1.0f);
}

// Smem layout (float offsets)
#define OFF_W1   0           // [51][208]
#define OFF_W2A  10608
#define OFF_W2B  21216
#define OFF_H1D  31824       // double buffer [2][52][128]  (duplicated pairs)
#define OFF_H2   45136       // double buffer [2][52][64]
#define OFF_B1   51792
#define OFF_WI1  52000
#define OFF_B2   52208
#define OFF_WL   52416       // 56
#define OFF_YP   52472       // [2][4][64]
#define SMEM_FLOATS 52984    // ~207 KB

#define HB1 6656             // 52*128
#define HB2 3328             // 52*64

__global__ __launch_bounds__(NTH, 1)
void lstm_rnn_kernel(const float* __restrict__ x,
                     const float* __restrict__ Wih1, const float* __restrict__ Whh1,
                     const float* __restrict__ bih1, const float* __restrict__ bhh1,
                     const float* __restrict__ Wih2, const float* __restrict__ Whh2,
                     const float* __restrict__ bih2, const float* __restrict__ bhh2,
                     const float* __restrict__ Wlin, const float* __restrict__ blin,
                     float* __restrict__ out)
{
    extern __shared__ float sm[];
    float* W1s  = sm + OFF_W1;
    float* W2as = sm + OFF_W2A;
    float* W2bs = sm + OFF_W2B;
    float* H1D  = sm + OFF_H1D;
    float* H2   = sm + OFF_H2;
    float* B1s  = sm + OFF_B1;
    float* WI1s = sm + OFF_WI1;
    float* B2s  = sm + OFF_B2;
    float* WLs  = sm + OFF_WL;
    float* YP   = sm + OFF_YP;

    const int tid = threadIdx.x;

    // ---- stage weights gate-interleaved, k-major: W[k][u*4+g] = Wxx[g*51+u][k]
    for (int idx = tid; idx < H_ * CP; idx += NTH) {
        int kk = idx / CP, c = idx - kk * CP;
        int u = c >> 2, g = c & 3;
        float w1 = 0.f, wa = 0.f, wb = 0.f;
        if (u < H_) {
            int j = g * H_ + u;
            w1 = Whh1[j * H_ + kk];
            wa = Wih2[j * H_ + kk];
            wb = Whh2[j * H_ + kk];
        }
        W1s[idx] = w1; W2as[idx] = wa; W2bs[idx] = wb;
    }
    for (int c = tid; c < CP; c += NTH) {
        int u = c >> 2, g = c & 3;
        bool v = (u < H_);
        int j = g * H_ + u;
        B1s[c]  = v ? (bih1[j] + bhh1[j]) : 0.f;
        WI1s[c] = v ? Wih1[j] : 0.f;
        B2s[c]  = v ? (bih2[j] + bhh2[j]) : 0.f;
    }
    if (tid < 53) WLs[tid] = (tid < H_) ? Wlin[tid] : ((tid == 52) ? blin[0] : 0.f);
    for (int idx = tid; idx < 2 * HB1; idx += NTH) H1D[idx] = 0.f;
    for (int idx = tid; idx < 2 * HB2; idx += NTH) H2[idx]  = 0.f;
    for (int idx = tid; idx < 512; idx += NTH) YP[idx] = 0.f;
    __syncthreads();

    // roles: warps 0-3 (grp0) = layer 1 + y writer; warps 4-7 (grp1) = layer 2
    const int grp  = tid >> 7;
    const int lt   = tid & 127;
    const int ug   = lt >> 5;        // warp-uniform u-slice [ug*13, ug*13+13)
    const int mg   = lt & 31;
    const int cb   = ug * 52;        // float offset of col slice
    const int mloc = mg * 2;
    const int m0   = blockIdx.x * M_;

    u64 acc[52];                     // shared register pool for both groups
    float c1r[26], c2r[26];
#pragma unroll
    for (int q = 0; q < 26; ++q) { c1r[q] = 0.f; c2r[q] = 0.f; }

    float xn0 = 0.f, xn1 = 0.f;

    // ---- prologue (grp0): gates1(0) = b1 + x(0)*Wih1  (h1(-1)=0) ----
    if (grp == 0) {
        float x00 = x[(size_t)(m0 + mloc + 0) * T_];
        float x01 = x[(size_t)(m0 + mloc + 1) * T_];
        u64 xd0 = pack2(x00, x00), xd1 = pack2(x01, x01);
        const ulonglong2* Bp = (const ulonglong2*)(B1s + cb);
        const ulonglong2* Wp = (const ulonglong2*)(WI1s + cb);
#pragma unroll
        for (int q = 0; q < 13; ++q) {
            ulonglong2 b2 = Bp[q], w2 = Wp[q];
            acc[4*q+0] = fma2(xd0, w2.x, b2.x);
            acc[4*q+1] = fma2(xd1, w2.x, b2.x);
            acc[4*q+2] = fma2(xd0, w2.y, b2.y);
            acc[4*q+3] = fma2(xd1, w2.y, b2.y);
        }
    }

    for (int i = 0; i <= T_; ++i) {
        // ================= Segment A =================
        if (grp == 0) {
            // prefetch x(i+1)
            int tn = (i + 1 < T_) ? (i + 1) : (T_ - 1);
            xn0 = x[(size_t)(m0 + mloc + 0) * T_ + tn];
            xn1 = x[(size_t)(m0 + mloc + 1) * T_ + tn];
            // y writer: step i-2 (partials written in segB(i-1), buffer i&1)
            if (lt < 64 && i >= 2) {
                const float* yp = YP + (i & 1) * 256;
                float y = WLs[52] + yp[lt] + yp[64 + lt] + yp[128 + lt] + yp[192 + lt];
                out[(size_t)(m0 + lt) * T_ + (i - 2)] = y;
            }
            // activation layer1, step i -> h1(i) (dup layout, buffer i&1)
            if (i < T_) {
                float* Hw = H1D + (i & 1) * HB1;
#pragma unroll
                for (int q = 0; q < 13; ++q) {
                    float hh0, hh1;
                    {
                        float iv, fv, gv, ov;
                        unpack2(acc[4*q+0], iv, fv);
                        unpack2(acc[4*q+2], gv, ov);
                        float c = sigm(fv) * c1r[2*q+0] + sigm(iv) * tanh_(gv);
                        c1r[2*q+0] = c;
                        hh0 = sigm(ov) * tanh_(c);
                    }
                    {
                        float iv, fv, gv, ov;
                        unpack2(acc[4*q+1], iv, fv);
                        unpack2(acc[4*q+3], gv, ov);
                        float c = sigm(fv) * c1r[2*q+1] + sigm(iv) * tanh_(gv);
                        c1r[2*q+1] = c;
                        hh1 = sigm(ov) * tanh_(c);
                    }
                    *(float4*)(Hw + (ug * 13 + q) * 128 + mg * 4) =
                        make_float4(hh0, hh0, hh1, hh1);
                }
            }
        } else {
            // GEMM layer2, step i-1: Wih2*h1(i-1) + Whh2*h2(i-2) + b2
            if (i >= 1) {
                {
                    const ulonglong2* Bp = (const ulonglong2*)(B2s + cb);
#pragma unroll
                    for (int q = 0; q < 13; ++q) {
                        ulonglong2 b2 = Bp[q];
                        acc[4*q+0] = b2.x; acc[4*q+1] = b2.x;
                        acc[4*q+2] = b2.y; acc[4*q+3] = b2.y;
                    }
                }
                const float* H1r = H1D + ((i - 1) & 1) * HB1;   // h1(i-1) dup
                const float* H2r = H2  + (i & 1) * HB2;         // h2(i-2)
                const float* wa0 = W2as + cb;
                const float* wb0 = W2bs + cb;
#pragma unroll 2
                for (int kk = 0; kk < H_; ++kk) {
                    ulonglong2 hv = *(const ulonglong2*)(H1r + kk * 128 + mg * 4);
                    float2 hb = *(const float2*)(H2r + kk * 64 + mloc);
                    u64 b0 = pack2(hb.x, hb.x), b1 = pack2(hb.y, hb.y);
                    const ulonglong2* wra = (const ulonglong2*)(wa0 + kk * CP);
                    const ulonglong2* wrb = (const ulonglong2*)(wb0 + kk * CP);
#pragma unroll
                    for (int q = 0; q < 13; ++q) {
                        ulonglong2 wa = wra[q];
                        acc[4*q+0] = fma2(hv.x, wa.x, acc[4*q+0]);
                        acc[4*q+1] = fma2(hv.y, wa.x, acc[4*q+1]);
                        acc[4*q+2] = fma2(hv.x, wa.y, acc[4*q+2]);
                        acc[4*q+3] = fma2(hv.y, wa.y, acc[4*q+3]);
                        ulonglong2 wb = wrb[q];
                        acc[4*q+0] = fma2(b0, wb.x, acc[4*q+0]);
                        acc[4*q+1] = fma2(b1, wb.x, acc[4*q+1]);
                        acc[4*q+2] = fma2(b0, wb.y, acc[4*q+2]);
                        acc[4*q+3] = fma2(b1, wb.y, acc[4*q+3]);
                    }
                }
            }
        }
        __syncthreads();

        // ================= Segment B =================
        if (grp == 0) {
            // GEMM layer1, step i+1: Whh1*h1(i) + x(i+1)*Wih1 + b1
            if (i + 1 < T_) {
                {
                    u64 xd0 = pack2(xn0, xn0), xd1 = pack2(xn1, xn1);
                    const ulonglong2* Bp = (const ulonglong2*)(B1s + cb);
                    const ulonglong2* Wp = (const ulonglong2*)(WI1s + cb);
#pragma unroll
                    for (int q = 0; q < 13; ++q) {
                        ulonglong2 b2 = Bp[q], w2 = Wp[q];
                        acc[4*q+0] = fma2(xd0, w2.x, b2.x);
                        acc[4*q+1] = fma2(xd1, w2.x, b2.x);
                        acc[4*q+2] = fma2(xd0, w2.y, b2.y);
                        acc[4*q+3] = fma2(xd1, w2.y, b2.y);
                    }
                }
                const float* Hr  = H1D + (i & 1) * HB1;          // h1(i) dup
                const float* wb0 = W1s + cb;
#pragma unroll 3
                for (int kk = 0; kk < H_; ++kk) {
                    ulonglong2 hv = *(const ulonglong2*)(Hr + kk * 128 + mg * 4);
                    const ulonglong2* wr = (const ulonglong2*)(wb0 + kk * CP);
#pragma unroll
                    for (int q = 0; q < 13; ++q) {
                        ulonglong2 w2 = wr[q];
                        acc[4*q+0] = fma2(hv.x, w2.x, acc[4*q+0]);
                        acc[4*q+1] = fma2(hv.y, w2.x, acc[4*q+1]);
                        acc[4*q+2] = fma2(hv.x, w2.y, acc[4*q+2]);
                        acc[4*q+3] = fma2(hv.y, w2.y, acc[4*q+3]);
                    }
                }
            }
        } else {
            // activation layer2, step i-1 -> h2(i-1), y partials
            if (i >= 1) {
                float* Hw = H2 + ((i - 1) & 1) * HB2;
                float py0 = 0.f, py1 = 0.f;
#pragma unroll
                for (int q = 0; q < 13; ++q) {
                    float hh0, hh1;
                    {
                        float iv, fv, gv, ov;
                        unpack2(acc[4*q+0], iv, fv);
                        unpack2(acc[4*q+2], gv, ov);
                        float c = sigm(fv) * c2r[2*q+0] + sigm(iv) * tanh_(gv);
                        c2r[2*q+0] = c;
                        hh0 = sigm(ov) * tanh_(c);
                    }
                    {
                        float iv, fv, gv, ov;
                        unpack2(acc[4*q+1], iv, fv);
                        unpack2(acc[4*q+3], gv, ov);
                        float c = sigm(fv) * c2r[2*q+1] + sigm(iv) * tanh_(gv);
                        c2r[2*q+1] = c;
                        hh1 = sigm(ov) * tanh_(c);
                    }
                    *(float2*)(Hw + (ug * 13 + q) * 64 + mloc) = make_float2(hh0, hh1);
                    float wl = WLs[ug * 13 + q];
                    py0 = fmaf(wl, hh0, py0);
                    py1 = fmaf(wl, hh1, py1);
                }
                *(float2*)(YP + ((i - 1) & 1) * 256 + ug * 64 + mloc) =
                    make_float2(py0, py1);
            }
        }
        __syncthreads();
    }

    // final y for step T-1 (partials in buffer (T-1)&1)
    if (tid < 64) {
        const float* yp = YP + ((T_ - 1) & 1) * 256;
        float y = WLs[52] + yp[tid] + yp[64 + tid] + yp[128 + tid] + yp[192 + tid];
        out[(size_t)(m0 + tid) * T_ + (T_ - 1)] = y;
    }
}

extern "C" void kernel_launch(void* const* d_in, const int* in_sizes, int n_in,
                              void* d_out, int out_size) {
    const float* x    = (const float*)d_in[0];
    const float* Wih1 = (const float*)d_in[1];
    const float* Whh1 = (const float*)d_in[2];
    const float* bih1 = (const float*)d_in[3];
    const float* bhh1 = (const float*)d_in[4];
    const float* Wih2 = (const float*)d_in[5];
    const float* Whh2 = (const float*)d_in[6];
    const float* bih2 = (const float*)d_in[7];
    const float* bhh2 = (const float*)d_in[8];
    const float* Wlin = (const float*)d_in[9];
    const float* blin = (const float*)d_in[10];
    float* out = (float*)d_out;

    size_t smem = SMEM_FLOATS * sizeof(float);   // ~207 KB
    cudaFuncSetAttribute(lstm_rnn_kernel,
                         cudaFuncAttributeMaxDynamicSharedMemorySize, (int)smem);
    lstm_rnn_kernel<<<B_ / M_, NTH, smem>>>(x, Wih1, Whh1, bih1, bhh1,
                                            Wih2, Whh2, bih2, bhh2,
                                            Wlin, blin, out);
}